// round 1
// baseline (speedup 1.0000x reference)
#include <cuda_runtime.h>
#include <math.h>

// ---------------------------------------------------------------------------
// Only batch row B-1 (=255) contributes to the output, and batch rows are
// independent -> compute a single-sequence 2-layer LSTM.
//
// Persistent-CTA design:
//   64 CTAs, 256 threads. CTA b owns hidden units [b*8, b*8+8) for BOTH cells.
//   All weight rows for those units (4 gates x (Whh1 row 512 + Wih2 row 512 +
//   Whh2 row 512)) live in shared memory (196 KB). Cell states c1/c2 are
//   CTA-local. Per step, CTAs exchange only h1/h2 (512 floats each) through
//   global scratch, separated by a global sense-reversing barrier (2/step).
// ---------------------------------------------------------------------------

#define HH     512
#define NBLK   64
#define NTHR   256
#define UNITS  8      // hidden units per block (512/64)

// smem layout (in floats)
#define OFF_W1    0        // 32 rows x 512  = 16384
#define OFF_W2    16384    // 32 rows x 1024 = 32768   [Wih2 row | Whh2 row]
#define OFF_WLIN  49152    // 512
#define OFF_H1    49664    // 512
#define OFF_H2    50176    // 512
#define OFF_G     50688    // 32
#define OFF_B1    50720    // 32
#define OFF_B2    50752    // 32
#define OFF_WX    50784    // 32
#define OFF_C1    50816    // 8
#define OFF_C2    50824    // 8
#define OFF_RED   50832    // 8
#define OFF_SX    50840    // 1
#define OFF_BLIN  50841    // 1
#define SMEM_FLOATS 50848

__device__ unsigned g_cnt = 0;
__device__ volatile unsigned g_gen = 0;
__device__ float g_h1[HH];
__device__ float g_h2[HH];

__device__ __forceinline__ float sigf(float v) { return 1.0f / (1.0f + expf(-v)); }

__device__ __forceinline__ void gbar(unsigned& lgen) {
    __syncthreads();
    if (threadIdx.x == 0) {
        __threadfence();
        unsigned arr = atomicAdd(&g_cnt, 1u);
        if (arr == gridDim.x - 1) {
            g_cnt = 0;
            __threadfence();
            g_gen = lgen + 1;
        } else {
            while (g_gen != lgen + 1) { }
            __threadfence();
        }
    }
    lgen += 1;
    __syncthreads();
}

__global__ void __launch_bounds__(NTHR, 1) lstm_seq_kernel(
    const float* __restrict__ input,
    const float* __restrict__ Wih1, const float* __restrict__ Whh1,
    const float* __restrict__ bih1, const float* __restrict__ bhh1,
    const float* __restrict__ Wih2, const float* __restrict__ Whh2,
    const float* __restrict__ bih2, const float* __restrict__ bhh2,
    const float* __restrict__ Wlin, const float* __restrict__ blin,
    float* __restrict__ out, int T, int pred_len, int Brows)
{
    extern __shared__ float smem[];
    float* sW1   = smem + OFF_W1;
    float* sW2   = smem + OFF_W2;
    float* sWlin = smem + OFF_WLIN;
    float* sh1   = smem + OFF_H1;
    float* sh2   = smem + OFF_H2;
    float* sg    = smem + OFF_G;
    float* sb1   = smem + OFF_B1;
    float* sb2   = smem + OFF_B2;
    float* swx   = smem + OFF_WX;
    float* sc1   = smem + OFF_C1;
    float* sc2   = smem + OFF_C2;
    float* sred  = smem + OFF_RED;

    const int tid  = threadIdx.x;
    const int wid  = tid >> 5;
    const int lane = tid & 31;
    const int b8   = blockIdx.x * UNITS;

    // ---- load this CTA's weight rows into smem ----
    // local row r = gate*8 + k  ->  global row R = gate*512 + b8 + k
    for (int idx = tid; idx < 32 * 128; idx += NTHR) {     // in float4 units
        int r  = idx >> 7;
        int k4 = idx & 127;
        int R  = ((r >> 3) << 9) + b8 + (r & 7);
        ((float4*)sW1)[idx]               = ((const float4*)Whh1)[R * 128 + k4];
        ((float4*)sW2)[r * 256 + k4]       = ((const float4*)Wih2)[R * 128 + k4];
        ((float4*)sW2)[r * 256 + 128 + k4] = ((const float4*)Whh2)[R * 128 + k4];
    }
    for (int i = tid; i < 128; i += NTHR)
        ((float4*)sWlin)[i] = ((const float4*)Wlin)[i];
    if (tid < 32) {
        int R = ((tid >> 3) << 9) + b8 + (tid & 7);
        sb1[tid] = bih1[R] + bhh1[R];
        sb2[tid] = bih2[R] + bhh2[R];
        swx[tid] = Wih1[R];               // Wih1 is (4H,1)
    }
    if (tid < UNITS) {
        sc1[tid] = 0.f; sc2[tid] = 0.f;
        g_h1[b8 + tid] = 0.f;
        g_h2[b8 + tid] = 0.f;
    }
    for (int i = tid; i < HH; i += NTHR) sh1[i] = 0.f;
    if (tid == 0) smem[OFF_BLIN] = blin[0];

    // barrier generation, read before this block's first arrival
    __shared__ unsigned s_gen0;
    if (tid == 0) s_gen0 = g_gen;
    __syncthreads();
    unsigned lgen = s_gen0;

    gbar(lgen);   // h1/h2 zeros + weights visible everywhere

    const int total = T + pred_len - 1;
    const float sblin = smem[OFF_BLIN];

    for (int t = 0; t < total; ++t) {
        // ---- stage h2(t-1) ----
        for (int i = tid; i < HH; i += NTHR) sh2[i] = __ldcg(&g_h2[i]);
        __syncthreads();

        // ---- x_t ----
        if (t < T) {
            if (tid == 0) smem[OFF_SX] = input[(size_t)(Brows - 1) * T + t];
        } else {
            // x = Wlin . h2(t-1) + blin   (redundant per block; block0 emits output)
            float p = 0.f;
            for (int i = tid; i < HH; i += NTHR) p += sWlin[i] * sh2[i];
            #pragma unroll
            for (int o = 16; o; o >>= 1) p += __shfl_xor_sync(0xffffffffu, p, o);
            if (lane == 0) sred[wid] = p;
            __syncthreads();
            if (tid == 0) {
                float s = sred[0];
                #pragma unroll
                for (int w = 1; w < 8; ++w) s += sred[w];
                s += sblin;
                smem[OFF_SX] = s;
                if (blockIdx.x == 0) out[t - T] = s;
            }
        }
        __syncthreads();
        const float x = smem[OFF_SX];

        // ---- phase 1: cell 1 gates (K = 512, uses sh1 = h1(t-1)) ----
        {
            float4 hv[4];
            #pragma unroll
            for (int m = 0; m < 4; ++m) hv[m] = ((const float4*)sh1)[lane + 32 * m];
            float acc[4] = {0.f, 0.f, 0.f, 0.f};
            #pragma unroll
            for (int rr = 0; rr < 4; ++rr) {
                const float4* wr = (const float4*)sW1 + (wid * 4 + rr) * 128 + lane;
                #pragma unroll
                for (int m = 0; m < 4; ++m) {
                    float4 wv = wr[32 * m];
                    acc[rr] += wv.x * hv[m].x + wv.y * hv[m].y + wv.z * hv[m].z + wv.w * hv[m].w;
                }
            }
            #pragma unroll
            for (int rr = 0; rr < 4; ++rr) {
                float a = acc[rr];
                #pragma unroll
                for (int o = 16; o; o >>= 1) a += __shfl_xor_sync(0xffffffffu, a, o);
                if (lane == 0) {
                    int r = wid * 4 + rr;
                    sg[r] = a + sb1[r] + x * swx[r];
                }
            }
        }
        __syncthreads();
        if (tid < UNITS) {
            float i_ = sigf(sg[tid]);
            float f_ = sigf(sg[8 + tid]);
            float gg = tanhf(sg[16 + tid]);
            float o_ = sigf(sg[24 + tid]);
            float c  = f_ * sc1[tid] + i_ * gg;
            sc1[tid] = c;
            __stcg(&g_h1[b8 + tid], o_ * tanhf(c));
        }

        gbar(lgen);   // h1(t) visible

        // ---- phase 2: cell 2 gates (K = 1024 over [h1(t); h2(t-1)]) ----
        for (int i = tid; i < HH; i += NTHR) sh1[i] = __ldcg(&g_h1[i]);
        __syncthreads();
        {
            float4 hv1[4], hv2[4];
            #pragma unroll
            for (int m = 0; m < 4; ++m) {
                hv1[m] = ((const float4*)sh1)[lane + 32 * m];
                hv2[m] = ((const float4*)sh2)[lane + 32 * m];
            }
            float acc[4] = {0.f, 0.f, 0.f, 0.f};
            #pragma unroll
            for (int rr = 0; rr < 4; ++rr) {
                const float4* wr = (const float4*)sW2 + (wid * 4 + rr) * 256 + lane;
                #pragma unroll
                for (int m = 0; m < 4; ++m) {
                    float4 wv = wr[32 * m];
                    acc[rr] += wv.x * hv1[m].x + wv.y * hv1[m].y + wv.z * hv1[m].z + wv.w * hv1[m].w;
                }
                #pragma unroll
                for (int m = 0; m < 4; ++m) {
                    float4 wv = wr[128 + 32 * m];
                    acc[rr] += wv.x * hv2[m].x + wv.y * hv2[m].y + wv.z * hv2[m].z + wv.w * hv2[m].w;
                }
            }
            #pragma unroll
            for (int rr = 0; rr < 4; ++rr) {
                float a = acc[rr];
                #pragma unroll
                for (int o = 16; o; o >>= 1) a += __shfl_xor_sync(0xffffffffu, a, o);
                if (lane == 0) {
                    int r = wid * 4 + rr;
                    sg[r] = a + sb2[r];
                }
            }
        }
        __syncthreads();
        if (tid < UNITS) {
            float i_ = sigf(sg[tid]);
            float f_ = sigf(sg[8 + tid]);
            float gg = tanhf(sg[16 + tid]);
            float o_ = sigf(sg[24 + tid]);
            float c  = f_ * sc2[tid] + i_ * gg;
            sc2[tid] = c;
            __stcg(&g_h2[b8 + tid], o_ * tanhf(c));
        }

        gbar(lgen);   // h2(t) visible
    }

    // ---- final output: o(total-1) ----
    if (blockIdx.x == 0) {
        for (int i = tid; i < HH; i += NTHR) sh2[i] = __ldcg(&g_h2[i]);
        __syncthreads();
        float p = 0.f;
        for (int i = tid; i < HH; i += NTHR) p += sWlin[i] * sh2[i];
        #pragma unroll
        for (int o = 16; o; o >>= 1) p += __shfl_xor_sync(0xffffffffu, p, o);
        if (lane == 0) sred[wid] = p;
        __syncthreads();
        if (tid == 0) {
            float s = sred[0];
            #pragma unroll
            for (int w = 1; w < 8; ++w) s += sred[w];
            out[pred_len - 1] = s + sblin;
        }
    }
}

extern "C" void kernel_launch(void* const* d_in, const int* in_sizes, int n_in,
                              void* d_out, int out_size) {
    // metadata order: input, pred_len, Wih1, Whh1, bih1, bhh1, Wih2, Whh2,
    //                 bih2, bhh2, Wlin, blin
    // pred_len may or may not be materialized as a buffer; detect via size.
    int off = (n_in >= 12 && in_sizes[1] == 1) ? 2 : 1;

    const float* input = (const float*)d_in[0];
    const float* Wih1  = (const float*)d_in[off + 0];
    const float* Whh1  = (const float*)d_in[off + 1];
    const float* bih1  = (const float*)d_in[off + 2];
    const float* bhh1  = (const float*)d_in[off + 3];
    const float* Wih2  = (const float*)d_in[off + 4];
    const float* Whh2  = (const float*)d_in[off + 5];
    const float* bih2  = (const float*)d_in[off + 6];
    const float* bhh2  = (const float*)d_in[off + 7];
    const float* Wlin  = (const float*)d_in[off + 8];
    const float* blin  = (const float*)d_in[off + 9];

    const int B = 256;
    const int T = in_sizes[0] / B;
    const int pred_len = out_size;   // output shape is (pred_len,)

    size_t shmem = (size_t)SMEM_FLOATS * sizeof(float);
    cudaFuncSetAttribute(lstm_seq_kernel,
                         cudaFuncAttributeMaxDynamicSharedMemorySize, (int)shmem);

    lstm_seq_kernel<<<NBLK, NTHR, shmem>>>(
        input, Wih1, Whh1, bih1, bhh1, Wih2, Whh2, bih2, bhh2, Wlin, blin,
        (float*)d_out, T, pred_len, B);
}

// round 2
// speedup vs baseline: 1.9755x; 1.9755x over previous
#include <cuda_runtime.h>
#include <math.h>

// ---------------------------------------------------------------------------
// Only batch row 255 reaches the output -> single-sequence 2-layer LSTM.
//
// Pipelined persistent kernel, 96 CTAs x 256 threads:
//   Group A (blocks 0..31):  layer-1, 16 hidden units each (64 gate rows, K=512)
//   Group B (blocks 32..95): layer-2,  8 hidden units each (32 gate rows, K=1024)
// Weights live in REGISTERS (128 floats/thread). During encode the two layers
// run concurrently (wavefront over time): one global barrier per tick.
// AR decode is strictly sequential: 2 barriers per step.
// ---------------------------------------------------------------------------

#define HT    512
#define NA    32
#define NB    64
#define NBLK  96
#define NTHR  256

__device__ unsigned g_cnt = 0;
__device__ volatile unsigned g_gen = 0;
__device__ float g_h1[2][HT];
__device__ float g_h2[2][HT];
__device__ float g_opart[NB];

__device__ __forceinline__ float sigf(float v)   { return 1.0f / (1.0f + __expf(-v)); }
__device__ __forceinline__ float tanhff(float v) { return 2.0f / (1.0f + __expf(-2.0f * v)) - 1.0f; }

__device__ __forceinline__ void gbar(unsigned& lgen) {
    __syncthreads();
    if (threadIdx.x == 0) {
        __threadfence();
        unsigned arr = atomicAdd(&g_cnt, 1u);
        if (arr == NBLK - 1) {
            g_cnt = 0;
            __threadfence();
            g_gen = lgen + 1;
        } else {
            while (g_gen != lgen + 1) { }
            __threadfence();
        }
    }
    lgen += 1;
    __syncthreads();
}

__global__ void __launch_bounds__(NTHR, 1) lstm_pipe_kernel(
    const float* __restrict__ input,
    const float* __restrict__ Wih1, const float* __restrict__ Whh1,
    const float* __restrict__ bih1, const float* __restrict__ bhh1,
    const float* __restrict__ Wih2, const float* __restrict__ Whh2,
    const float* __restrict__ bih2, const float* __restrict__ bhh2,
    const float* __restrict__ Wlin, const float* __restrict__ blin,
    float* __restrict__ out, int T, int pred_len, int Brows)
{
    __shared__ float sh1[HT];
    __shared__ float sh2[HT];
    __shared__ float sg[64];
    __shared__ float sact[64];
    __shared__ float sb[64];
    __shared__ float swx[64];
    __shared__ float sc[16];
    __shared__ float swlin[8];
    __shared__ float sxs[1];
    __shared__ unsigned sgen0;

    const int tid  = threadIdx.x;
    const int wid  = tid >> 5;
    const int lane = tid & 31;
    const bool isA = (blockIdx.x < NA);

    if (blockIdx.x == 0) {
        for (int i = tid; i < HT; i += NTHR) { g_h1[0][i] = 0.f; g_h2[0][i] = 0.f; }
    }

    if (tid == 0) sgen0 = g_gen;

    int ph1 = 0, ph2 = 0;
    const int total_enc = T;   // encode ticks 0..T (T+1 ticks)

    if (isA) {
        // ================= GROUP A : layer 1 =================
        const int bA = blockIdx.x * 16;
        float wA[8][16];
        #pragma unroll
        for (int rr = 0; rr < 8; ++rr) {
            int r = wid * 8 + rr;
            int R = ((r >> 4) << 9) + bA + (r & 15);
            const float* Wr = Whh1 + (size_t)R * HT;
            #pragma unroll
            for (int m = 0; m < 16; ++m) wA[rr][m] = Wr[lane + 32 * m];
        }
        if (tid < 64) {
            int r = tid;
            int R = ((r >> 4) << 9) + bA + (r & 15);
            sb[r]  = bih1[R] + bhh1[R];
            swx[r] = Wih1[R];
        }
        if (tid < 16) sc[tid] = 0.f;
        const float blin0 = blin[0];
        const float* xin = input + (size_t)(Brows - 1) * T;

        __syncthreads();
        unsigned lgen = sgen0;
        gbar(lgen);  // initial state visible

        // ---------- A step macro ----------
        #define A_STEP(XVAL)                                                        \
        {                                                                           \
            for (int i = tid; i < HT; i += NTHR) sh1[i] = __ldcg(&g_h1[ph1][i]);     \
            __syncthreads();                                                        \
            float hv[16];                                                           \
            _Pragma("unroll")                                                       \
            for (int m = 0; m < 16; ++m) hv[m] = sh1[lane + 32 * m];                 \
            _Pragma("unroll")                                                       \
            for (int rr = 0; rr < 8; ++rr) {                                        \
                float a = 0.f;                                                      \
                _Pragma("unroll")                                                   \
                for (int m = 0; m < 16; ++m) a = fmaf(wA[rr][m], hv[m], a);          \
                _Pragma("unroll")                                                   \
                for (int o = 16; o; o >>= 1) a += __shfl_xor_sync(0xffffffffu, a, o);\
                if (lane == 0) sg[wid * 8 + rr] = a;                                 \
            }                                                                       \
            __syncthreads();                                                        \
            if (tid < 64) {                                                         \
                float v = sg[tid] + sb[tid] + (XVAL) * swx[tid];                     \
                sact[tid] = ((tid >> 4) == 2) ? tanhff(v) : sigf(v);                 \
            }                                                                       \
            __syncthreads();                                                        \
            if (tid < 16) {                                                         \
                float c = sact[16 + tid] * sc[tid] + sact[tid] * sact[32 + tid];     \
                sc[tid] = c;                                                        \
                __stcg(&g_h1[ph1 ^ 1][bA + tid], sact[48 + tid] * tanhff(c));        \
            }                                                                       \
        }

        // encode
        for (int k = 0; k <= total_enc; ++k) {
            if (k < T) {
                float x = __ldg(&xin[k]);
                A_STEP(x);
            }
            gbar(lgen);
            ph1 ^= (k < T) ? 1 : 0;
            ph2 ^= (k >= 1) ? 1 : 0;
        }

        // AR decode
        for (int s = 1; s < pred_len; ++s) {
            float x;
            if (wid == 0) {
                float v = __ldcg(&g_opart[lane]) + __ldcg(&g_opart[lane + 32]);
                #pragma unroll
                for (int o = 16; o; o >>= 1) v += __shfl_xor_sync(0xffffffffu, v, o);
                if (lane == 0) sxs[0] = v + blin0;
            }
            __syncthreads();
            x = sxs[0];
            if (blockIdx.x == 0 && tid == 0) out[s - 1] = x;
            A_STEP(x);
            gbar(lgen); ph1 ^= 1;
            gbar(lgen); ph2 ^= 1;
        }

        if (blockIdx.x == 0 && wid == 0) {
            float v = __ldcg(&g_opart[lane]) + __ldcg(&g_opart[lane + 32]);
            #pragma unroll
            for (int o = 16; o; o >>= 1) v += __shfl_xor_sync(0xffffffffu, v, o);
            if (lane == 0) out[pred_len - 1] = v + blin0;
        }
        #undef A_STEP
    } else {
        // ================= GROUP B : layer 2 =================
        const int jB = blockIdx.x - NA;
        const int bB = jB * 8;
        float wB[4][32];
        #pragma unroll
        for (int rr = 0; rr < 4; ++rr) {
            int r = wid * 4 + rr;
            int R = ((r >> 3) << 9) + bB + (r & 7);
            const float* Wi = Wih2 + (size_t)R * HT;
            const float* Wh = Whh2 + (size_t)R * HT;
            #pragma unroll
            for (int m = 0; m < 16; ++m) {
                wB[rr][m]      = Wi[lane + 32 * m];
                wB[rr][16 + m] = Wh[lane + 32 * m];
            }
        }
        if (tid < 32) {
            int r = tid;
            int R = ((r >> 3) << 9) + bB + (r & 7);
            sb[r] = bih2[R] + bhh2[R];
        }
        if (tid < 8)  { sc[tid] = 0.f; swlin[tid] = Wlin[bB + tid]; }

        __syncthreads();
        unsigned lgen = sgen0;
        gbar(lgen);

        #define B_STEP(DO_O)                                                        \
        {                                                                           \
            for (int i = tid; i < HT; i += NTHR) {                                   \
                sh1[i] = __ldcg(&g_h1[ph1][i]);                                      \
                sh2[i] = __ldcg(&g_h2[ph2][i]);                                      \
            }                                                                       \
            __syncthreads();                                                        \
            float hv[32];                                                           \
            _Pragma("unroll")                                                       \
            for (int m = 0; m < 16; ++m) {                                          \
                hv[m]      = sh1[lane + 32 * m];                                     \
                hv[16 + m] = sh2[lane + 32 * m];                                     \
            }                                                                       \
            _Pragma("unroll")                                                       \
            for (int rr = 0; rr < 4; ++rr) {                                        \
                float a = 0.f;                                                      \
                _Pragma("unroll")                                                   \
                for (int m = 0; m < 32; ++m) a = fmaf(wB[rr][m], hv[m], a);          \
                _Pragma("unroll")                                                   \
                for (int o = 16; o; o >>= 1) a += __shfl_xor_sync(0xffffffffu, a, o);\
                if (lane == 0) sg[wid * 4 + rr] = a;                                 \
            }                                                                       \
            __syncthreads();                                                        \
            if (wid == 0) {                                                         \
                float v = sg[lane] + sb[lane];                                       \
                float a = ((lane >> 3) == 2) ? tanhff(v) : sigf(v);                  \
                int kk = lane & 7;                                                  \
                float i_ = __shfl_sync(0xffffffffu, a, kk);                          \
                float f_ = __shfl_sync(0xffffffffu, a, kk + 8);                      \
                float g_ = __shfl_sync(0xffffffffu, a, kk + 16);                     \
                float o_ = __shfl_sync(0xffffffffu, a, kk + 24);                     \
                float p = 0.f;                                                      \
                if (lane < 8) {                                                     \
                    float c = f_ * sc[lane] + i_ * g_;                               \
                    sc[lane] = c;                                                   \
                    float hh = o_ * tanhff(c);                                       \
                    __stcg(&g_h2[ph2 ^ 1][bB + lane], hh);                           \
                    p = swlin[lane] * hh;                                            \
                }                                                                   \
                p += __shfl_xor_sync(0xffffffffu, p, 4);                             \
                p += __shfl_xor_sync(0xffffffffu, p, 2);                             \
                p += __shfl_xor_sync(0xffffffffu, p, 1);                             \
                if ((DO_O) && lane == 0) __stcg(&g_opart[jB], p);                    \
            }                                                                       \
        }

        // encode
        for (int k = 0; k <= total_enc; ++k) {
            if (k >= 1) {
                B_STEP(k == T);
            }
            gbar(lgen);
            ph1 ^= (k < T) ? 1 : 0;
            ph2 ^= (k >= 1) ? 1 : 0;
        }

        // AR decode
        for (int s = 1; s < pred_len; ++s) {
            gbar(lgen); ph1 ^= 1;
            B_STEP(true);
            gbar(lgen); ph2 ^= 1;
        }
        #undef B_STEP
    }
}

extern "C" void kernel_launch(void* const* d_in, const int* in_sizes, int n_in,
                              void* d_out, int out_size) {
    int off = (n_in >= 12 && in_sizes[1] == 1) ? 2 : 1;

    const float* input = (const float*)d_in[0];
    const float* Wih1  = (const float*)d_in[off + 0];
    const float* Whh1  = (const float*)d_in[off + 1];
    const float* bih1  = (const float*)d_in[off + 2];
    const float* bhh1  = (const float*)d_in[off + 3];
    const float* Wih2  = (const float*)d_in[off + 4];
    const float* Whh2  = (const float*)d_in[off + 5];
    const float* bih2  = (const float*)d_in[off + 6];
    const float* bhh2  = (const float*)d_in[off + 7];
    const float* Wlin  = (const float*)d_in[off + 8];
    const float* blin  = (const float*)d_in[off + 9];

    const int B = 256;
    const int T = in_sizes[0] / B;
    const int pred_len = out_size;

    lstm_pipe_kernel<<<NBLK, NTHR>>>(
        input, Wih1, Whh1, bih1, bhh1, Wih2, Whh2, bih2, bhh2, Wlin, blin,
        (float*)d_out, T, pred_len, B);
}

// round 3
// speedup vs baseline: 2.0619x; 1.0437x over previous
#include <cuda_runtime.h>

// ---------------------------------------------------------------------------
// Single-sequence (batch row 255) 2-layer LSTM, dataflow-synchronized.
//
// 96 persistent CTAs x 256 threads:
//   Group A (blocks 0..31):  layer-1, 16 hidden units each (64 gate rows, K=512)
//   Group B (blocks 32..95): layer-2,  8 hidden units each (32 gate rows, K=1024)
// Weights in registers. NO global barrier: producers release-store h chunks and
// bump a per-CTA monotonic tick flag; consumers poll the flag group with one
// warp (relaxed loads + ballot) then acquire-fence. Ring depth 4 on h buffers.
// ---------------------------------------------------------------------------

#define HT   512
#define NA   32
#define NBG  64
#define NBLK 96
#define NTHR 256

__device__ int   g_fA[NA * 32];    // padded: one flag per 128B
__device__ int   g_fB[NBG * 32];
__device__ float g_h1b[4][HT];
__device__ float g_h2b[4][HT];
__device__ float g_ob[4][NBG];

__device__ __forceinline__ float sigf(float v)   { return 1.0f / (1.0f + __expf(-v)); }
__device__ __forceinline__ float tanhff(float v) { return 2.0f / (1.0f + __expf(-2.0f * v)) - 1.0f; }
__device__ __forceinline__ void fence_gpu() { asm volatile("fence.acq_rel.gpu;" ::: "memory"); }
__device__ __forceinline__ int  ld_flag(const int* p) {
    int v; asm volatile("ld.relaxed.gpu.global.b32 %0, [%1];" : "=r"(v) : "l"(p) : "memory"); return v;
}
__device__ __forceinline__ void st_flag(int* p, int v) {
    asm volatile("st.relaxed.gpu.global.b32 [%0], %1;" :: "l"(p), "r"(v) : "memory");
}

// warp-0 poll: all A flags >= needA, all B flags >= needB
__device__ __forceinline__ void pollAB(int needA, int needB, int lane) {
    const int* fa  = &g_fA[lane * 32];
    const int* fb0 = &g_fB[lane * 32];
    const int* fb1 = &g_fB[(lane + 32) * 32];
    for (;;) {
        int a  = ld_flag(fa);
        int b0 = ld_flag(fb0);
        int b1 = ld_flag(fb1);
        bool ok = (a >= needA) && (b0 >= needB) && (b1 >= needB);
        if (__ballot_sync(0xffffffffu, ok) == 0xffffffffu) break;
    }
    fence_gpu();
}

__global__ void init_state_kernel() {
    int tid = threadIdx.x;
    for (int i = tid; i < NA * 32;  i += NTHR) g_fA[i] = 0;
    for (int i = tid; i < NBG * 32; i += NTHR) g_fB[i] = 0;
    for (int i = tid; i < 4 * HT;   i += NTHR) { ((float*)g_h1b)[i] = 0.f; ((float*)g_h2b)[i] = 0.f; }
    for (int i = tid; i < 4 * NBG;  i += NTHR) ((float*)g_ob)[i] = 0.f;
}

__global__ void __launch_bounds__(NTHR, 1) lstm_flow_kernel(
    const float* __restrict__ input,
    const float* __restrict__ Wih1, const float* __restrict__ Whh1,
    const float* __restrict__ bih1, const float* __restrict__ bhh1,
    const float* __restrict__ Wih2, const float* __restrict__ Whh2,
    const float* __restrict__ bih2, const float* __restrict__ bhh2,
    const float* __restrict__ Wlin, const float* __restrict__ blin,
    float* __restrict__ out, int T, int pred_len, int Brows)
{
    __shared__ float sg[64];
    __shared__ float sb[64];
    __shared__ float swx[64];
    __shared__ float swlin[8];
    __shared__ float sxs;
    __shared__ float sxin[1024];

    const int tid  = threadIdx.x;
    const int wid  = tid >> 5;
    const int lane = tid & 31;
    const int total = T + pred_len - 1;

    if (blockIdx.x < NA) {
        // ===================== GROUP A : layer 1 =====================
        const int bA = blockIdx.x * 16;
        float wA[8][16];
        #pragma unroll
        for (int rr = 0; rr < 8; ++rr) {
            int r = wid * 8 + rr;
            int R = ((r >> 4) << 9) + bA + (r & 15);
            const float* Wr = Whh1 + (size_t)R * HT;
            #pragma unroll
            for (int m = 0; m < 16; ++m) wA[rr][m] = Wr[lane + 32 * m];
        }
        if (tid < 64) {
            int r = tid;
            int R = ((r >> 4) << 9) + bA + (r & 15);
            sb[r]  = bih1[R] + bhh1[R];
            swx[r] = Wih1[R];
        }
        const float* xin = input + (size_t)(Brows - 1) * T;
        for (int i = tid; i < T && i < 1024; i += NTHR) sxin[i] = xin[i];
        const float blin0 = blin[0];
        float c1 = 0.f;     // cell state, warp0 lanes<16
        __syncthreads();

        for (int t = 0; t < total; ++t) {
            if (wid == 0) {
                int needA = t;
                int needB = (t >= T) ? t : (t > 3 ? t - 3 : 0);
                pollAB(needA, needB, lane);
                if (t >= T) {
                    const float* ob = g_ob[(t - 1) & 3];
                    float ov = __ldcg(&ob[lane]) + __ldcg(&ob[lane + 32]);
                    #pragma unroll
                    for (int o = 16; o; o >>= 1) ov += __shfl_xor_sync(0xffffffffu, ov, o);
                    if (lane == 0) {
                        float xv = ov + blin0;
                        sxs = xv;
                        if (blockIdx.x == 0) out[t - T] = xv;
                    }
                }
            }
            __syncthreads();
            const float x = (t < T) ? ((t < 1024) ? sxin[t] : __ldg(&xin[t])) : sxs;

            const float* hp = g_h1b[(t + 3) & 3];
            float hv[16];
            #pragma unroll
            for (int m = 0; m < 16; ++m) hv[m] = __ldcg(&hp[lane + 32 * m]);
            #pragma unroll
            for (int rr = 0; rr < 8; ++rr) {
                float a = 0.f;
                #pragma unroll
                for (int m = 0; m < 16; ++m) a = fmaf(wA[rr][m], hv[m], a);
                #pragma unroll
                for (int o = 16; o; o >>= 1) a += __shfl_xor_sync(0xffffffffu, a, o);
                if (lane == 0) sg[wid * 8 + rr] = a;
            }
            __syncthreads();

            if (wid == 0) {
                float v0 = sg[lane]      + sb[lane]      + x * swx[lane];
                float v1 = sg[lane + 32] + sb[lane + 32] + x * swx[lane + 32];
                float a0 = sigf(v0);                                   // gates i, f
                float a1 = (lane < 16) ? tanhff(v1) : sigf(v1);        // gates g, o
                int u = lane & 15;
                float i_ = __shfl_sync(0xffffffffu, a0, u);
                float f_ = __shfl_sync(0xffffffffu, a0, u + 16);
                float g_ = __shfl_sync(0xffffffffu, a1, u);
                float o_ = __shfl_sync(0xffffffffu, a1, u + 16);
                if (lane < 16) {
                    c1 = f_ * c1 + i_ * g_;
                    __stcg(&g_h1b[t & 3][bA + lane], o_ * tanhff(c1));
                }
                __syncwarp();
                if (lane == 0) {
                    fence_gpu();
                    st_flag(&g_fA[blockIdx.x * 32], t + 1);
                }
            }
        }

        // epilogue: o(total-1) -> out[pred_len-1]
        if (blockIdx.x == 0 && wid == 0) {
            const int* fb0 = &g_fB[lane * 32];
            const int* fb1 = &g_fB[(lane + 32) * 32];
            for (;;) {
                bool ok = (ld_flag(fb0) >= total) && (ld_flag(fb1) >= total);
                if (__ballot_sync(0xffffffffu, ok) == 0xffffffffu) break;
            }
            fence_gpu();
            const float* ob = g_ob[(total - 1) & 3];
            float ov = __ldcg(&ob[lane]) + __ldcg(&ob[lane + 32]);
            #pragma unroll
            for (int o = 16; o; o >>= 1) ov += __shfl_xor_sync(0xffffffffu, ov, o);
            if (lane == 0) out[pred_len - 1] = ov + blin0;
        }
    } else {
        // ===================== GROUP B : layer 2 =====================
        const int jB = blockIdx.x - NA;
        const int bB = jB * 8;
        float wB[4][32];
        #pragma unroll
        for (int rr = 0; rr < 4; ++rr) {
            int r = wid * 4 + rr;
            int R = ((r >> 3) << 9) + bB + (r & 7);
            const float* Wi = Wih2 + (size_t)R * HT;
            const float* Wh = Whh2 + (size_t)R * HT;
            #pragma unroll
            for (int m = 0; m < 16; ++m) {
                wB[rr][m]      = Wi[lane + 32 * m];
                wB[rr][16 + m] = Wh[lane + 32 * m];
            }
        }
        if (tid < 32) {
            int r = tid;
            int R = ((r >> 3) << 9) + bB + (r & 7);
            sb[r] = bih2[R] + bhh2[R];
        }
        if (tid < 8) swlin[tid] = Wlin[bB + tid];
        float c2 = 0.f;     // cell state, warp0 lanes<8
        __syncthreads();

        for (int k = 0; k < total; ++k) {
            if (wid == 0) pollAB(k + 1, k, lane);
            __syncthreads();

            const float* h1p = g_h1b[k & 3];
            const float* h2p = g_h2b[(k + 3) & 3];
            float hv[32];
            #pragma unroll
            for (int m = 0; m < 16; ++m) {
                hv[m]      = __ldcg(&h1p[lane + 32 * m]);
                hv[16 + m] = __ldcg(&h2p[lane + 32 * m]);
            }
            #pragma unroll
            for (int rr = 0; rr < 4; ++rr) {
                float a = 0.f;
                #pragma unroll
                for (int m = 0; m < 32; ++m) a = fmaf(wB[rr][m], hv[m], a);
                #pragma unroll
                for (int o = 16; o; o >>= 1) a += __shfl_xor_sync(0xffffffffu, a, o);
                if (lane == 0) sg[wid * 4 + rr] = a;
            }
            __syncthreads();

            if (wid == 0) {
                float v = sg[lane] + sb[lane];
                float a = ((lane >> 3) == 2) ? tanhff(v) : sigf(v);
                int u = lane & 7;
                float i_ = __shfl_sync(0xffffffffu, a, u);
                float f_ = __shfl_sync(0xffffffffu, a, u + 8);
                float g_ = __shfl_sync(0xffffffffu, a, u + 16);
                float o_ = __shfl_sync(0xffffffffu, a, u + 24);
                float p = 0.f;
                if (lane < 8) {
                    c2 = f_ * c2 + i_ * g_;
                    float hh = o_ * tanhff(c2);
                    __stcg(&g_h2b[k & 3][bB + lane], hh);
                    p = swlin[lane] * hh;
                }
                p += __shfl_xor_sync(0xffffffffu, p, 4);
                p += __shfl_xor_sync(0xffffffffu, p, 2);
                p += __shfl_xor_sync(0xffffffffu, p, 1);
                __syncwarp();
                if (lane == 0) {
                    if (k >= T - 1) __stcg(&g_ob[k & 3][jB], p);
                    fence_gpu();
                    st_flag(&g_fB[jB * 32], k + 1);
                }
            }
        }
    }
}

extern "C" void kernel_launch(void* const* d_in, const int* in_sizes, int n_in,
                              void* d_out, int out_size) {
    int off = (n_in >= 12 && in_sizes[1] == 1) ? 2 : 1;

    const float* input = (const float*)d_in[0];
    const float* Wih1  = (const float*)d_in[off + 0];
    const float* Whh1  = (const float*)d_in[off + 1];
    const float* bih1  = (const float*)d_in[off + 2];
    const float* bhh1  = (const float*)d_in[off + 3];
    const float* Wih2  = (const float*)d_in[off + 4];
    const float* Whh2  = (const float*)d_in[off + 5];
    const float* bih2  = (const float*)d_in[off + 6];
    const float* bhh2  = (const float*)d_in[off + 7];
    const float* Wlin  = (const float*)d_in[off + 8];
    const float* blin  = (const float*)d_in[off + 9];

    const int B = 256;
    const int T = in_sizes[0] / B;
    const int pred_len = out_size;

    init_state_kernel<<<1, NTHR>>>();
    lstm_flow_kernel<<<NBLK, NTHR>>>(
        input, Wih1, Whh1, bih1, bhh1, Wih2, Whh2, bih2, bhh2, Wlin, blin,
        (float*)d_out, T, pred_len, B);
}

// round 4
// speedup vs baseline: 4.0622x; 1.9702x over previous
#include <cuda_runtime.h>

// ---------------------------------------------------------------------------
// Single-sequence (batch row 255) 2-layer LSTM.
// Dataflow sync via single-copy-atomic tagged (tick,value) 64-bit pairs:
// the load that discovers readiness IS the data load. No fences, no flags
// on the data path. 96 persistent CTAs (32 layer-1, 64 layer-2), weights in
// registers, distributed polling into smem.
// ---------------------------------------------------------------------------

#define HT   512
#define NA   32
#define NBG  64
#define NBLK 96
#define NTHR 256
#define R1   16   // h1 ring depth (A->B skew covered by backpressure)
#define R2   4    // h2 ring depth (B-B skew <= 1)
#define RO   4    // o  ring depth

typedef unsigned long long u64;

__device__ u64 g_h1p[R1][HT];
__device__ u64 g_h2p[R2][HT];
__device__ u64 g_op[RO][NBG];
__device__ int g_prog[NBG * 32];      // B progress flags, 128B padded

__device__ __forceinline__ float sigf(float v)   { return 1.0f / (1.0f + __expf(-v)); }
__device__ __forceinline__ float tanhff(float v) { return 2.0f / (1.0f + __expf(-2.0f * v)) - 1.0f; }

__device__ __forceinline__ u64 ldp(const u64* p) {
    u64 v; asm volatile("ld.relaxed.gpu.global.b64 %0, [%1];" : "=l"(v) : "l"(p) : "memory"); return v;
}
__device__ __forceinline__ void stp(u64* p, u64 v) {
    asm volatile("st.relaxed.gpu.global.b64 [%0], %1;" :: "l"(p), "l"(v) : "memory");
}
__device__ __forceinline__ int ldacq(const int* p) {
    int v; asm volatile("ld.acquire.gpu.global.b32 %0, [%1];" : "=r"(v) : "l"(p) : "memory"); return v;
}
__device__ __forceinline__ void strel(int* p, int v) {
    asm volatile("st.release.gpu.global.b32 [%0], %1;" :: "l"(p), "r"(v) : "memory");
}
__device__ __forceinline__ u64 mkpair(float f, unsigned tag) {
    return ((u64)tag << 32) | (u64)__float_as_uint(f);
}
__device__ __forceinline__ float pval(u64 v) { return __uint_as_float((unsigned)v); }
__device__ __forceinline__ unsigned ptag(u64 v) { return (unsigned)(v >> 32); }

__global__ void init_state_kernel() {
    int tid = threadIdx.x;
    for (int i = tid; i < R1 * HT;  i += NTHR) ((u64*)g_h1p)[i] = 0ull;  // tag 0, val 0
    for (int i = tid; i < R2 * HT;  i += NTHR) ((u64*)g_h2p)[i] = 0ull;
    for (int i = tid; i < RO * NBG; i += NTHR) ((u64*)g_op)[i]  = 0ull;
    for (int i = tid; i < NBG * 32; i += NTHR) g_prog[i] = 0;
}

__global__ void __launch_bounds__(NTHR, 1) lstm_tag_kernel(
    const float* __restrict__ input,
    const float* __restrict__ Wih1, const float* __restrict__ Whh1,
    const float* __restrict__ bih1, const float* __restrict__ bhh1,
    const float* __restrict__ Wih2, const float* __restrict__ Whh2,
    const float* __restrict__ bih2, const float* __restrict__ bhh2,
    const float* __restrict__ Wlin, const float* __restrict__ blin,
    float* __restrict__ out, int T, int pred_len, int Brows)
{
    __shared__ float sh1[HT];
    __shared__ float sh2[HT];
    __shared__ float sg[64];
    __shared__ float sb[64];
    __shared__ float swx[64];
    __shared__ float swlin[8];
    __shared__ float sxs;
    __shared__ float sxin[1024];

    const int tid  = threadIdx.x;
    const int wid  = tid >> 5;
    const int lane = tid & 31;
    const int total = T + pred_len - 1;

    if (blockIdx.x < NA) {
        // ===================== GROUP A : layer 1 =====================
        const int bA = blockIdx.x * 16;
        float wA[8][16];
        #pragma unroll
        for (int rr = 0; rr < 8; ++rr) {
            int r = wid * 8 + rr;
            int R = ((r >> 4) << 9) + bA + (r & 15);
            const float* Wr = Whh1 + (size_t)R * HT;
            #pragma unroll
            for (int m = 0; m < 16; ++m) wA[rr][m] = Wr[lane + 32 * m];
        }
        if (tid < 64) {
            int r = tid;
            int R = ((r >> 4) << 9) + bA + (r & 15);
            sb[r]  = bih1[R] + bhh1[R];
            swx[r] = Wih1[R];
        }
        const float* xin = input + (size_t)(Brows - 1) * T;
        for (int i = tid; i < T && i < 1024; i += NTHR) sxin[i] = xin[i];
        const float blin0 = blin[0];
        float c1 = 0.f;
        __syncthreads();

        for (int t = 0; t < total; ++t) {
            // ---- warp0 extras: backpressure (rare) + decode x poll ----
            if (wid == 0) {
                if ((t & 7) == 0 && t >= 16) {
                    int need = t - 8;
                    const int* pp0 = &g_prog[lane * 32];
                    const int* pp1 = &g_prog[(lane + 32) * 32];
                    for (;;) {
                        bool ok = (ldacq(pp0) >= need) && (ldacq(pp1) >= need);
                        if (__ballot_sync(0xffffffffu, ok) == 0xffffffffu) break;
                    }
                }
                if (t >= T) {
                    const u64* q0 = &g_op[t & (RO - 1)][lane];
                    const u64* q1 = q0 + 32;
                    u64 a0, a1;
                    for (;;) {
                        a0 = ldp(q0); a1 = ldp(q1);
                        bool ok = (ptag(a0) == (unsigned)t) && (ptag(a1) == (unsigned)t);
                        if (__ballot_sync(0xffffffffu, ok) == 0xffffffffu) break;
                    }
                    float ov = pval(a0) + pval(a1);
                    #pragma unroll
                    for (int o = 16; o; o >>= 1) ov += __shfl_xor_sync(0xffffffffu, ov, o);
                    if (lane == 0) {
                        float xv = ov + blin0;
                        sxs = xv;
                        if (blockIdx.x == 0) out[t - T] = xv;
                    }
                }
            }

            // ---- distributed pair poll: h1 tagged t ----
            {
                const u64* p0 = &g_h1p[t & (R1 - 1)][tid];
                const u64* p1 = p0 + 256;
                u64 v0, v1; bool o0 = false, o1 = false;
                do {
                    if (!o0) { v0 = ldp(p0); o0 = (ptag(v0) == (unsigned)t); }
                    if (!o1) { v1 = ldp(p1); o1 = (ptag(v1) == (unsigned)t); }
                } while (!(o0 && o1));
                sh1[tid]       = pval(v0);
                sh1[tid + 256] = pval(v1);
            }
            __syncthreads();

            // ---- gate matvec ----
            float hv[16];
            #pragma unroll
            for (int m = 0; m < 16; ++m) hv[m] = sh1[lane + 32 * m];
            #pragma unroll
            for (int rr = 0; rr < 8; ++rr) {
                float a = 0.f;
                #pragma unroll
                for (int m = 0; m < 16; ++m) a = fmaf(wA[rr][m], hv[m], a);
                #pragma unroll
                for (int o = 16; o; o >>= 1) a += __shfl_xor_sync(0xffffffffu, a, o);
                if (lane == 0) sg[wid * 8 + rr] = a;
            }
            __syncthreads();

            // ---- activation + publish h1(t) tagged t+1 ----
            if (wid == 0) {
                const float x = (t < T) ? ((t < 1024) ? sxin[t] : __ldg(&xin[t])) : sxs;
                float v0 = sg[lane]      + sb[lane]      + x * swx[lane];
                float v1 = sg[lane + 32] + sb[lane + 32] + x * swx[lane + 32];
                float a0 = sigf(v0);                              // gates i, f
                float a1 = (lane < 16) ? tanhff(v1) : sigf(v1);   // gates g, o
                int u = lane & 15;
                float i_ = __shfl_sync(0xffffffffu, a0, u);
                float f_ = __shfl_sync(0xffffffffu, a0, u + 16);
                float g_ = __shfl_sync(0xffffffffu, a1, u);
                float o_ = __shfl_sync(0xffffffffu, a1, u + 16);
                if (lane < 16) {
                    c1 = f_ * c1 + i_ * g_;
                    float hh = o_ * tanhff(c1);
                    stp(&g_h1p[(t + 1) & (R1 - 1)][bA + lane], mkpair(hh, (unsigned)(t + 1)));
                }
            }
        }

        // ---- epilogue: o(total-1) tagged 'total' -> out[pred_len-1] ----
        if (blockIdx.x == 0 && wid == 0) {
            const u64* q0 = &g_op[total & (RO - 1)][lane];
            const u64* q1 = q0 + 32;
            u64 a0, a1;
            for (;;) {
                a0 = ldp(q0); a1 = ldp(q1);
                bool ok = (ptag(a0) == (unsigned)total) && (ptag(a1) == (unsigned)total);
                if (__ballot_sync(0xffffffffu, ok) == 0xffffffffu) break;
            }
            float ov = pval(a0) + pval(a1);
            #pragma unroll
            for (int o = 16; o; o >>= 1) ov += __shfl_xor_sync(0xffffffffu, ov, o);
            if (lane == 0) out[pred_len - 1] = ov + blin0;
        }
    } else {
        // ===================== GROUP B : layer 2 =====================
        const int jB = blockIdx.x - NA;
        const int bB = jB * 8;
        float wB[4][32];
        #pragma unroll
        for (int rr = 0; rr < 4; ++rr) {
            int r = wid * 4 + rr;
            int R = ((r >> 3) << 9) + bB + (r & 7);
            const float* Wi = Wih2 + (size_t)R * HT;
            const float* Wh = Whh2 + (size_t)R * HT;
            #pragma unroll
            for (int m = 0; m < 16; ++m) {
                wB[rr][m]      = Wi[lane + 32 * m];
                wB[rr][16 + m] = Wh[lane + 32 * m];
            }
        }
        if (tid < 32) {
            int r = tid;
            int R = ((r >> 3) << 9) + bB + (r & 7);
            sb[r] = bih2[R] + bhh2[R];
        }
        if (tid < 8) swlin[tid] = Wlin[bB + tid];
        float c2 = 0.f;
        __syncthreads();

        for (int k = 0; k < total; ++k) {
            // ---- distributed pair poll: h1 tag k+1, h2 tag k ----
            {
                const u64* p0 = &g_h1p[(k + 1) & (R1 - 1)][tid];
                const u64* p1 = p0 + 256;
                const u64* q0 = &g_h2p[k & (R2 - 1)][tid];
                const u64* q1 = q0 + 256;
                u64 v0, v1, w0, w1;
                bool o0 = false, o1 = false, o2 = false, o3 = false;
                do {
                    if (!o2) { w0 = ldp(q0); o2 = (ptag(w0) == (unsigned)k); }
                    if (!o3) { w1 = ldp(q1); o3 = (ptag(w1) == (unsigned)k); }
                    if (!o0) { v0 = ldp(p0); o0 = (ptag(v0) == (unsigned)(k + 1)); }
                    if (!o1) { v1 = ldp(p1); o1 = (ptag(v1) == (unsigned)(k + 1)); }
                } while (!(o0 && o1 && o2 && o3));
                sh1[tid]       = pval(v0);
                sh1[tid + 256] = pval(v1);
                sh2[tid]       = pval(w0);
                sh2[tid + 256] = pval(w1);
            }
            __syncthreads();
            if (tid == 0) strel(&g_prog[jB * 32], k);   // all pair loads done

            // ---- gate matvec (K = 1024) ----
            float hv[32];
            #pragma unroll
            for (int m = 0; m < 16; ++m) {
                hv[m]      = sh1[lane + 32 * m];
                hv[16 + m] = sh2[lane + 32 * m];
            }
            #pragma unroll
            for (int rr = 0; rr < 4; ++rr) {
                float a = 0.f;
                #pragma unroll
                for (int m = 0; m < 32; ++m) a = fmaf(wB[rr][m], hv[m], a);
                #pragma unroll
                for (int o = 16; o; o >>= 1) a += __shfl_xor_sync(0xffffffffu, a, o);
                if (lane == 0) sg[wid * 4 + rr] = a;
            }
            __syncthreads();

            // ---- activation + publish h2(k) tag k+1, o partial tag k+1 ----
            if (wid == 0) {
                float v = sg[lane] + sb[lane];
                float a = ((lane >> 3) == 2) ? tanhff(v) : sigf(v);
                int u = lane & 7;
                float i_ = __shfl_sync(0xffffffffu, a, u);
                float f_ = __shfl_sync(0xffffffffu, a, u + 8);
                float g_ = __shfl_sync(0xffffffffu, a, u + 16);
                float o_ = __shfl_sync(0xffffffffu, a, u + 24);
                float p = 0.f;
                if (lane < 8) {
                    c2 = f_ * c2 + i_ * g_;
                    float hh = o_ * tanhff(c2);
                    stp(&g_h2p[(k + 1) & (R2 - 1)][bB + lane], mkpair(hh, (unsigned)(k + 1)));
                    p = swlin[lane] * hh;
                }
                p += __shfl_xor_sync(0xffffffffu, p, 4);
                p += __shfl_xor_sync(0xffffffffu, p, 2);
                p += __shfl_xor_sync(0xffffffffu, p, 1);
                if (lane == 0 && k >= T - 1)
                    stp(&g_op[(k + 1) & (RO - 1)][jB], mkpair(p, (unsigned)(k + 1)));
            }
        }
    }
}

extern "C" void kernel_launch(void* const* d_in, const int* in_sizes, int n_in,
                              void* d_out, int out_size) {
    int off = (n_in >= 12 && in_sizes[1] == 1) ? 2 : 1;

    const float* input = (const float*)d_in[0];
    const float* Wih1  = (const float*)d_in[off + 0];
    const float* Whh1  = (const float*)d_in[off + 1];
    const float* bih1  = (const float*)d_in[off + 2];
    const float* bhh1  = (const float*)d_in[off + 3];
    const float* Wih2  = (const float*)d_in[off + 4];
    const float* Whh2  = (const float*)d_in[off + 5];
    const float* bih2  = (const float*)d_in[off + 6];
    const float* bhh2  = (const float*)d_in[off + 7];
    const float* Wlin  = (const float*)d_in[off + 8];
    const float* blin  = (const float*)d_in[off + 9];

    const int B = 256;
    const int T = in_sizes[0] / B;
    const int pred_len = out_size;

    init_state_kernel<<<1, NTHR>>>();
    lstm_tag_kernel<<<NBLK, NTHR>>>(
        input, Wih1, Whh1, bih1, bhh1, Wih2, Whh2, bih2, bhh2, Wlin, blin,
        (float*)d_out, T, pred_len, B);
}

// round 5
// speedup vs baseline: 4.0958x; 1.0083x over previous
#include <cuda_runtime.h>

// ---------------------------------------------------------------------------
// Single-sequence (batch row 255) 2-layer LSTM.
// Dataflow sync via single-copy-atomic tagged (tick,value) 64-bit pairs.
// Round 5: packed fp32x2 FMA (fma.rn.f32x2) for the gate matvecs -> half the
// FMA instruction issue; u64 LDS for h vectors -> half the LDS instructions.
// ---------------------------------------------------------------------------

#define HT   512
#define NA   32
#define NBG  64
#define NBLK 96
#define NTHR 256
#define R1   16   // h1 ring depth (A->B skew covered by backpressure)
#define R2   4    // h2 ring depth (B-B skew <= 1)
#define RO   4    // o  ring depth

typedef unsigned long long u64;

__device__ u64 g_h1p[R1][HT];
__device__ u64 g_h2p[R2][HT];
__device__ u64 g_op[RO][NBG];
__device__ int g_prog[NBG * 32];      // B progress flags, 128B padded

__device__ __forceinline__ float sigf(float v)   { return 1.0f / (1.0f + __expf(-v)); }
__device__ __forceinline__ float tanhff(float v) { return 2.0f / (1.0f + __expf(-2.0f * v)) - 1.0f; }

__device__ __forceinline__ u64 ldp(const u64* p) {
    u64 v; asm volatile("ld.relaxed.gpu.global.b64 %0, [%1];" : "=l"(v) : "l"(p) : "memory"); return v;
}
__device__ __forceinline__ void stp(u64* p, u64 v) {
    asm volatile("st.relaxed.gpu.global.b64 [%0], %1;" :: "l"(p), "l"(v) : "memory");
}
__device__ __forceinline__ int ldacq(const int* p) {
    int v; asm volatile("ld.acquire.gpu.global.b32 %0, [%1];" : "=r"(v) : "l"(p) : "memory"); return v;
}
__device__ __forceinline__ void strel(int* p, int v) {
    asm volatile("st.release.gpu.global.b32 [%0], %1;" :: "l"(p), "r"(v) : "memory");
}
__device__ __forceinline__ u64 mkpair(float f, unsigned tag) {
    return ((u64)tag << 32) | (u64)__float_as_uint(f);
}
__device__ __forceinline__ float pval(u64 v) { return __uint_as_float((unsigned)v); }
__device__ __forceinline__ unsigned ptag(u64 v) { return (unsigned)(v >> 32); }

// packed fp32x2 fused multiply-add (Blackwell double-rate fp32 pipe)
__device__ __forceinline__ u64 fma2(u64 a, u64 b, u64 c) {
    u64 d;
    asm("fma.rn.f32x2 %0, %1, %2, %3;" : "=l"(d) : "l"(a), "l"(b), "l"(c));
    return d;
}
__device__ __forceinline__ float hsum2(u64 a) {
    return __uint_as_float((unsigned)a) + __uint_as_float((unsigned)(a >> 32));
}

__global__ void init_state_kernel() {
    int tid = threadIdx.x;
    for (int i = tid; i < R1 * HT;  i += NTHR) ((u64*)g_h1p)[i] = 0ull;  // tag 0, val 0
    for (int i = tid; i < R2 * HT;  i += NTHR) ((u64*)g_h2p)[i] = 0ull;
    for (int i = tid; i < RO * NBG; i += NTHR) ((u64*)g_op)[i]  = 0ull;
    for (int i = tid; i < NBG * 32; i += NTHR) g_prog[i] = 0;
}

__global__ void __launch_bounds__(NTHR, 1) lstm_x2_kernel(
    const float* __restrict__ input,
    const float* __restrict__ Wih1, const float* __restrict__ Whh1,
    const float* __restrict__ bih1, const float* __restrict__ bhh1,
    const float* __restrict__ Wih2, const float* __restrict__ Whh2,
    const float* __restrict__ bih2, const float* __restrict__ bhh2,
    const float* __restrict__ Wlin, const float* __restrict__ blin,
    float* __restrict__ out, int T, int pred_len, int Brows)
{
    __shared__ __align__(16) float sh1[HT];
    __shared__ __align__(16) float sh2[HT];
    __shared__ float sg[64];
    __shared__ float sb[64];
    __shared__ float swx[64];
    __shared__ float swlin[8];
    __shared__ float sxs;
    __shared__ float sxin[1024];

    const int tid  = threadIdx.x;
    const int wid  = tid >> 5;
    const int lane = tid & 31;
    const int total = T + pred_len - 1;

    if (blockIdx.x < NA) {
        // ===================== GROUP A : layer 1 =====================
        const int bA = blockIdx.x * 16;
        u64 wA2[8][8];   // 8 rows x 8 f32x2 pairs (K=512 over 32 lanes)
        #pragma unroll
        for (int rr = 0; rr < 8; ++rr) {
            int r = wid * 8 + rr;
            int R = ((r >> 4) << 9) + bA + (r & 15);
            const u64* Wr2 = (const u64*)(Whh1 + (size_t)R * HT);
            #pragma unroll
            for (int p = 0; p < 8; ++p) wA2[rr][p] = Wr2[lane + 32 * p];
        }
        if (tid < 64) {
            int r = tid;
            int R = ((r >> 4) << 9) + bA + (r & 15);
            sb[r]  = bih1[R] + bhh1[R];
            swx[r] = Wih1[R];
        }
        const float* xin = input + (size_t)(Brows - 1) * T;
        for (int i = tid; i < T && i < 1024; i += NTHR) sxin[i] = xin[i];
        const float blin0 = blin[0];
        float c1 = 0.f;
        __syncthreads();

        for (int t = 0; t < total; ++t) {
            // ---- warp0 extras: backpressure (rare) + decode x poll ----
            if (wid == 0) {
                if ((t & 7) == 0 && t >= 16) {
                    int need = t - 8;
                    const int* pp0 = &g_prog[lane * 32];
                    const int* pp1 = &g_prog[(lane + 32) * 32];
                    for (;;) {
                        bool ok = (ldacq(pp0) >= need) && (ldacq(pp1) >= need);
                        if (__ballot_sync(0xffffffffu, ok) == 0xffffffffu) break;
                    }
                }
                if (t >= T) {
                    const u64* q0 = &g_op[t & (RO - 1)][lane];
                    const u64* q1 = q0 + 32;
                    u64 a0, a1;
                    for (;;) {
                        a0 = ldp(q0); a1 = ldp(q1);
                        bool ok = (ptag(a0) == (unsigned)t) && (ptag(a1) == (unsigned)t);
                        if (__ballot_sync(0xffffffffu, ok) == 0xffffffffu) break;
                    }
                    float ov = pval(a0) + pval(a1);
                    #pragma unroll
                    for (int o = 16; o; o >>= 1) ov += __shfl_xor_sync(0xffffffffu, ov, o);
                    if (lane == 0) {
                        float xv = ov + blin0;
                        sxs = xv;
                        if (blockIdx.x == 0) out[t - T] = xv;
                    }
                }
            }

            // ---- distributed pair poll: h1 tagged t ----
            {
                const u64* p0 = &g_h1p[t & (R1 - 1)][tid];
                const u64* p1 = p0 + 256;
                u64 v0, v1; bool o0 = false, o1 = false;
                do {
                    if (!o0) { v0 = ldp(p0); o0 = (ptag(v0) == (unsigned)t); }
                    if (!o1) { v1 = ldp(p1); o1 = (ptag(v1) == (unsigned)t); }
                } while (!(o0 && o1));
                sh1[tid]       = pval(v0);
                sh1[tid + 256] = pval(v1);
            }
            __syncthreads();

            // ---- gate matvec (packed f32x2) ----
            u64 hv2[8];
            #pragma unroll
            for (int p = 0; p < 8; ++p) hv2[p] = ((const u64*)sh1)[lane + 32 * p];
            #pragma unroll
            for (int rr = 0; rr < 8; ++rr) {
                u64 acc = 0ull;
                #pragma unroll
                for (int p = 0; p < 8; ++p) acc = fma2(wA2[rr][p], hv2[p], acc);
                float a = hsum2(acc);
                #pragma unroll
                for (int o = 16; o; o >>= 1) a += __shfl_xor_sync(0xffffffffu, a, o);
                if (lane == 0) sg[wid * 8 + rr] = a;
            }
            __syncthreads();

            // ---- activation + publish h1(t) tagged t+1 ----
            if (wid == 0) {
                const float x = (t < T) ? ((t < 1024) ? sxin[t] : __ldg(&xin[t])) : sxs;
                float v0 = sg[lane]      + sb[lane]      + x * swx[lane];
                float v1 = sg[lane + 32] + sb[lane + 32] + x * swx[lane + 32];
                float a0 = sigf(v0);                              // gates i, f
                float a1 = (lane < 16) ? tanhff(v1) : sigf(v1);   // gates g, o
                int u = lane & 15;
                float i_ = __shfl_sync(0xffffffffu, a0, u);
                float f_ = __shfl_sync(0xffffffffu, a0, u + 16);
                float g_ = __shfl_sync(0xffffffffu, a1, u);
                float o_ = __shfl_sync(0xffffffffu, a1, u + 16);
                if (lane < 16) {
                    c1 = f_ * c1 + i_ * g_;
                    float hh = o_ * tanhff(c1);
                    stp(&g_h1p[(t + 1) & (R1 - 1)][bA + lane], mkpair(hh, (unsigned)(t + 1)));
                }
            }
        }

        // ---- epilogue: o(total-1) tagged 'total' -> out[pred_len-1] ----
        if (blockIdx.x == 0 && wid == 0) {
            const u64* q0 = &g_op[total & (RO - 1)][lane];
            const u64* q1 = q0 + 32;
            u64 a0, a1;
            for (;;) {
                a0 = ldp(q0); a1 = ldp(q1);
                bool ok = (ptag(a0) == (unsigned)total) && (ptag(a1) == (unsigned)total);
                if (__ballot_sync(0xffffffffu, ok) == 0xffffffffu) break;
            }
            float ov = pval(a0) + pval(a1);
            #pragma unroll
            for (int o = 16; o; o >>= 1) ov += __shfl_xor_sync(0xffffffffu, ov, o);
            if (lane == 0) out[pred_len - 1] = ov + blin0;
        }
    } else {
        // ===================== GROUP B : layer 2 =====================
        const int jB = blockIdx.x - NA;
        const int bB = jB * 8;
        u64 wB2[4][16];  // 4 rows x 16 f32x2 pairs (K=1024 over 32 lanes)
        #pragma unroll
        for (int rr = 0; rr < 4; ++rr) {
            int r = wid * 4 + rr;
            int R = ((r >> 3) << 9) + bB + (r & 7);
            const u64* Wi2 = (const u64*)(Wih2 + (size_t)R * HT);
            const u64* Wh2 = (const u64*)(Whh2 + (size_t)R * HT);
            #pragma unroll
            for (int p = 0; p < 8; ++p) {
                wB2[rr][p]     = Wi2[lane + 32 * p];
                wB2[rr][8 + p] = Wh2[lane + 32 * p];
            }
        }
        if (tid < 32) {
            int r = tid;
            int R = ((r >> 3) << 9) + bB + (r & 7);
            sb[r] = bih2[R] + bhh2[R];
        }
        if (tid < 8) swlin[tid] = Wlin[bB + tid];
        float c2 = 0.f;
        __syncthreads();

        for (int k = 0; k < total; ++k) {
            // ---- distributed pair poll: h1 tag k+1, h2 tag k ----
            {
                const u64* p0 = &g_h1p[(k + 1) & (R1 - 1)][tid];
                const u64* p1 = p0 + 256;
                const u64* q0 = &g_h2p[k & (R2 - 1)][tid];
                const u64* q1 = q0 + 256;
                u64 v0, v1, w0, w1;
                bool o0 = false, o1 = false, o2 = false, o3 = false;
                do {
                    if (!o2) { w0 = ldp(q0); o2 = (ptag(w0) == (unsigned)k); }
                    if (!o3) { w1 = ldp(q1); o3 = (ptag(w1) == (unsigned)k); }
                    if (!o0) { v0 = ldp(p0); o0 = (ptag(v0) == (unsigned)(k + 1)); }
                    if (!o1) { v1 = ldp(p1); o1 = (ptag(v1) == (unsigned)(k + 1)); }
                } while (!(o0 && o1 && o2 && o3));
                sh1[tid]       = pval(v0);
                sh1[tid + 256] = pval(v1);
                sh2[tid]       = pval(w0);
                sh2[tid + 256] = pval(w1);
            }
            __syncthreads();
            if (tid == 0) strel(&g_prog[jB * 32], k);   // all pair loads done

            // ---- gate matvec (K = 1024, packed f32x2) ----
            u64 hv2[16];
            #pragma unroll
            for (int p = 0; p < 8; ++p) {
                hv2[p]     = ((const u64*)sh1)[lane + 32 * p];
                hv2[8 + p] = ((const u64*)sh2)[lane + 32 * p];
            }
            #pragma unroll
            for (int rr = 0; rr < 4; ++rr) {
                u64 acc = 0ull;
                #pragma unroll
                for (int p = 0; p < 16; ++p) acc = fma2(wB2[rr][p], hv2[p], acc);
                float a = hsum2(acc);
                #pragma unroll
                for (int o = 16; o; o >>= 1) a += __shfl_xor_sync(0xffffffffu, a, o);
                if (lane == 0) sg[wid * 4 + rr] = a;
            }
            __syncthreads();

            // ---- activation + publish h2(k) tag k+1, o partial tag k+1 ----
            if (wid == 0) {
                float v = sg[lane] + sb[lane];
                float a = ((lane >> 3) == 2) ? tanhff(v) : sigf(v);
                int u = lane & 7;
                float i_ = __shfl_sync(0xffffffffu, a, u);
                float f_ = __shfl_sync(0xffffffffu, a, u + 8);
                float g_ = __shfl_sync(0xffffffffu, a, u + 16);
                float o_ = __shfl_sync(0xffffffffu, a, u + 24);
                float p = 0.f;
                if (lane < 8) {
                    c2 = f_ * c2 + i_ * g_;
                    float hh = o_ * tanhff(c2);
                    stp(&g_h2p[(k + 1) & (R2 - 1)][bB + lane], mkpair(hh, (unsigned)(k + 1)));
                    p = swlin[lane] * hh;
                }
                p += __shfl_xor_sync(0xffffffffu, p, 4);
                p += __shfl_xor_sync(0xffffffffu, p, 2);
                p += __shfl_xor_sync(0xffffffffu, p, 1);
                if (lane == 0 && k >= T - 1)
                    stp(&g_op[(k + 1) & (RO - 1)][jB], mkpair(p, (unsigned)(k + 1)));
            }
        }
    }
}

extern "C" void kernel_launch(void* const* d_in, const int* in_sizes, int n_in,
                              void* d_out, int out_size) {
    int off = (n_in >= 12 && in_sizes[1] == 1) ? 2 : 1;

    const float* input = (const float*)d_in[0];
    const float* Wih1  = (const float*)d_in[off + 0];
    const float* Whh1  = (const float*)d_in[off + 1];
    const float* bih1  = (const float*)d_in[off + 2];
    const float* bhh1  = (const float*)d_in[off + 3];
    const float* Wih2  = (const float*)d_in[off + 4];
    const float* Whh2  = (const float*)d_in[off + 5];
    const float* bih2  = (const float*)d_in[off + 6];
    const float* bhh2  = (const float*)d_in[off + 7];
    const float* Wlin  = (const float*)d_in[off + 8];
    const float* blin  = (const float*)d_in[off + 9];

    const int B = 256;
    const int T = in_sizes[0] / B;
    const int pred_len = out_size;

    init_state_kernel<<<1, NTHR>>>();
    lstm_x2_kernel<<<NBLK, NTHR>>>(
        input, Wih1, Whh1, bih1, bhh1, Wih2, Whh2, bih2, bhh2, Wlin, blin,
        (float*)d_out, T, pred_len, B);
}